// round 13
// baseline (speedup 1.0000x reference)
#include <cuda_runtime.h>
#include <cstdint>

#define N_NODES  100000
#define N_EDGES  1600000
#define D        128
#define N_LAYERS 7
#define N_GRAPHS 64
#define N_CLASSES 10
#define SNN_IN   512
#define SNN_HID  1024
#define SNN_BETA 0.85f

// ---------------- scratch (no allocations allowed) ----------------
__device__ float g_h0[N_NODES * D];
__device__ float g_h1[N_NODES * D];
__device__ uint32_t g_ah[N_NODES * 64];   // agg hi plane (bf16x2, 2 vals/word)
__device__ uint32_t g_al[N_NODES * 64];   // agg lo plane
__device__ int   g_counts[N_NODES];
__device__ int   g_rowptr[N_NODES + 1];
__device__ int   g_wptr[N_NODES];
__device__ int   g_esrc[N_EDGES];
__device__ int   g_blocksums[256];
__device__ float g_pool[N_GRAPHS * D];
__device__ float g_cnt[N_GRAPHS];
__device__ float g_snnh[N_GRAPHS * SNN_HID];
__device__ int   g_flags[2];   // [0]: edge_index is int64, [1]: batch is int64
// packed bf16x2 split weights: [l][mat][part][n][kword]  (2 k per word)
__device__ uint32_t g_wsp[N_LAYERS * 2 * 2 * D * (D / 2)];

// ---------------- portable tensor-core helpers (sm_80+ ISA only) ----------------
__device__ __forceinline__ uint32_t pack_bf16(float lo, float hi) {
    uint32_t r;
    asm("cvt.rn.bf16x2.f32 %0, %1, %2;" : "=r"(r) : "f"(hi), "f"(lo));
    return r;
}
__device__ __forceinline__ void mma_bf16(float* d, const uint32_t* a, uint32_t b0, uint32_t b1) {
    asm volatile(
        "mma.sync.aligned.m16n8k16.row.col.f32.bf16.bf16.f32 "
        "{%0,%1,%2,%3}, {%4,%5,%6,%7}, {%8,%9}, {%0,%1,%2,%3};"
        : "+f"(d[0]), "+f"(d[1]), "+f"(d[2]), "+f"(d[3])
        : "r"(a[0]), "r"(a[1]), "r"(a[2]), "r"(a[3]), "r"(b0), "r"(b1));
}
__device__ __forceinline__ void ldsm_x4(uint32_t* r, uint32_t addr) {
    asm volatile("ldmatrix.sync.aligned.m8n8.x4.shared.b16 {%0,%1,%2,%3}, [%4];"
        : "=r"(r[0]), "=r"(r[1]), "=r"(r[2]), "=r"(r[3]) : "r"(addr));
}
__device__ __forceinline__ uint32_t smem_u32(const void* p) {
    uint32_t a;
    asm("{ .reg .u64 t; cvta.to.shared.u64 t, %1; cvt.u32.u64 %0, t; }" : "=r"(a) : "l"(p));
    return a;
}
// split two floats into packed bf16 hi word + residual lo word
__device__ __forceinline__ void split2(float f0, float f1, uint32_t& hw, uint32_t& lw) {
    hw = pack_bf16(f0, f1);
    float f0h = __uint_as_float(hw << 16);
    float f1h = __uint_as_float(hw & 0xFFFF0000u);
    lw = pack_bf16(f0 - f0h, f1 - f1h);
}

// ---------------- index-width helpers ----------------
__device__ __forceinline__ int ld_idx(const void* p, long long i, int is64) {
    if (is64) return (int)((const long long*)p)[i];
    return ((const int*)p)[i];
}

__global__ void k_noop() {}

// Parallel dtype detection
__global__ void k_detect(const unsigned int* ei, const unsigned int* bt) {
    __shared__ int e64s, b64s;
    int t = threadIdx.x;   // 256
    if (t == 0) { e64s = 1; b64s = 1; }
    __syncthreads();
    if (ei[2 * t + 1] != 0u) e64s = 0;
    if (bt[99999 - 2 * t] != 0u) b64s = 0;
    __syncthreads();
    if (t == 0) { g_flags[0] = e64s; g_flags[1] = b64s; }
}

// Transpose + bf16 hi/lo split of all layer weights, packed 2-k-per-word.
__global__ void k_wprep(const float* __restrict__ wrel, const float* __restrict__ wroot) {
    int idx = blockIdx.x * 256 + threadIdx.x;
    const int WORDS = N_LAYERS * 2 * D * (D / 2);   // 114688
    if (idx >= WORDS) return;
    int l = idx >> 14;
    int rem = idx & 16383;
    int mat = rem >> 13;
    int r2 = rem & 8191;
    int n = r2 >> 6;
    int wk = r2 & 63;
    int k = wk * 2;
    const float* W = (mat ? wroot : wrel) + (long long)l * D * D;
    float f0 = W[k * D + n];
    float f1 = W[(k + 1) * D + n];
    uint32_t hw, lw;
    split2(f0, f1, hw, lw);
    int base = ((l * 2 + mat) * 2) * 8192 + n * 64 + wk;
    g_wsp[base] = hw;
    g_wsp[base + 8192] = lw;
}

// ---------------- CSR build ----------------
__global__ void k_zero_counts() {
    int i = blockIdx.x * blockDim.x + threadIdx.x;
    if (i < N_NODES) g_counts[i] = 0;
}
__global__ void k_hist(const void* ei) {
    int e = blockIdx.x * blockDim.x + threadIdx.x;
    if (e >= N_EDGES) return;
    int dst = ld_idx(ei, (long long)N_EDGES + e, g_flags[0]);
    atomicAdd(&g_counts[dst], 1);
}
__global__ void k_scan1() {
    __shared__ int s[1024];
    int blk = blockIdx.x, t = threadIdx.x;
    int idx = blk * 1024 + t;
    int v = (idx < N_NODES) ? g_counts[idx] : 0;
    s[t] = v;
    __syncthreads();
    for (int off = 1; off < 1024; off <<= 1) {
        int add = (t >= off) ? s[t - off] : 0;
        __syncthreads();
        s[t] += add;
        __syncthreads();
    }
    if (idx < N_NODES) g_rowptr[idx] = s[t];
    if (t == 1023) g_blocksums[blk] = s[t];
}
__global__ void k_scan2(int nblocks) {
    if (blockIdx.x == 0 && threadIdx.x == 0) {
        int acc = 0;
        for (int b = 0; b < nblocks; b++) { int v = g_blocksums[b]; g_blocksums[b] = acc; acc += v; }
        g_rowptr[N_NODES] = N_EDGES;
    }
}
__global__ void k_scan3() {
    int i = blockIdx.x * blockDim.x + threadIdx.x;
    if (i < N_NODES) {
        int ex = g_rowptr[i] - g_counts[i] + g_blocksums[i >> 10];
        g_rowptr[i] = ex;
        g_wptr[i] = ex;
    }
}
__global__ void k_scatter(const void* ei) {
    int e = blockIdx.x * blockDim.x + threadIdx.x;
    if (e >= N_EDGES) return;
    int is64 = g_flags[0];
    int src = ld_idx(ei, e, is64);
    int dst = ld_idx(ei, (long long)N_EDGES + e, is64);
    int pos = atomicAdd(&g_wptr[dst], 1);
    g_esrc[pos] = src;
}

// ---------------- aggregation: warp per node, writes pre-split bf16 planes ----
__global__ void k_agg(const float* __restrict__ h,
                      uint32_t* __restrict__ aggh, uint32_t* __restrict__ aggl) {
    int node = (blockIdx.x * blockDim.x + threadIdx.x) >> 5;
    int lane = threadIdx.x & 31;
    if (node >= N_NODES) return;
    int s = g_rowptr[node];
    int e = g_rowptr[node + 1];
    float4 a0 = make_float4(0.f, 0.f, 0.f, 0.f);
    float4 a1 = make_float4(0.f, 0.f, 0.f, 0.f);
    int i = s;
    for (; i + 4 <= e; i += 4) {
        int s0 = g_esrc[i];
        int s1 = g_esrc[i + 1];
        int s2 = g_esrc[i + 2];
        int s3 = g_esrc[i + 3];
        float4 v0 = *(const float4*)&h[(long long)s0 * D + lane * 4];
        float4 v1 = *(const float4*)&h[(long long)s1 * D + lane * 4];
        float4 v2 = *(const float4*)&h[(long long)s2 * D + lane * 4];
        float4 v3 = *(const float4*)&h[(long long)s3 * D + lane * 4];
        a0.x += v0.x; a0.y += v0.y; a0.z += v0.z; a0.w += v0.w;
        a1.x += v1.x; a1.y += v1.y; a1.z += v1.z; a1.w += v1.w;
        a0.x += v2.x; a0.y += v2.y; a0.z += v2.z; a0.w += v2.w;
        a1.x += v3.x; a1.y += v3.y; a1.z += v3.z; a1.w += v3.w;
    }
    for (; i < e; i++) {
        int s0 = g_esrc[i];
        float4 v0 = *(const float4*)&h[(long long)s0 * D + lane * 4];
        a0.x += v0.x; a0.y += v0.y; a0.z += v0.z; a0.w += v0.w;
    }
    a0.x += a1.x; a0.y += a1.y; a0.z += a1.z; a0.w += a1.w;
    uint32_t h01, l01, h23, l23;
    split2(a0.x, a0.y, h01, l01);
    split2(a0.z, a0.w, h23, l23);
    *(uint2*)&aggh[(long long)node * 64 + lane * 2] = make_uint2(h01, h23);
    *(uint2*)&aggl[(long long)node * 64 + lane * 2] = make_uint2(l01, l23);
}

// ---------------- shared GEMM pieces -----------------------------------------
#define RSTR 80
#define SM_AH 0
#define SM_AL 10240
#define SM_BH 20480
#define SM_BL 30720
#define BUFSZ 40960
#define GEMM_SMEM (2 * BUFSZ)

// partial = h @ W2 + bias   (independent of agg; overlaps with k_agg on s2)
__global__ __launch_bounds__(256, 2)
void k_gemm_h(const float* __restrict__ A2,
              const uint32_t* __restrict__ Wt,   // W2 tiles: hi at 0, lo at +8192
              const float* __restrict__ bias, float* __restrict__ C) {
    extern __shared__ __align__(16) char smc[];
    const uint32_t sbase = smem_u32(smc);
    const int tid = threadIdx.x;
    const int w = tid >> 5;
    const int lane = tid & 31;
    const int g = lane >> 2;
    const int tg = lane & 3;
    const int bm = blockIdx.x * 128;
    const int mbase = (w & 3) * 32;
    const int nbase = (w >> 2) * 64;

    float acc[2][8][4];
#pragma unroll
    for (int mt = 0; mt < 2; mt++)
#pragma unroll
        for (int nt = 0; nt < 8; nt++)
#pragma unroll
            for (int q = 0; q < 4; q++) acc[mt][nt][q] = 0.f;

    const int srow = tid >> 3;
    const int sq = tid & 7;

    float4 pf[4];
#pragma unroll
    for (int it = 0; it < 4; it++) {
        int row = it * 32 + srow;
        pf[it] = (bm + row < N_NODES)
                 ? *(const float4*)&A2[(long long)(bm + row) * 128 + sq * 4]
                 : make_float4(0.f, 0.f, 0.f, 0.f);
    }
#pragma unroll
    for (int it = 0; it < 4; it++) {
        int row = it * 32 + srow;
        uint32_t off = (uint32_t)(row * RSTR + sq * 8);
        float4 v = pf[it];
        uint32_t h01, l01, h23, l23;
        split2(v.x, v.y, h01, l01);
        split2(v.z, v.w, h23, l23);
        *(uint2*)(smc + SM_AH + off) = make_uint2(h01, h23);
        *(uint2*)(smc + SM_AL + off) = make_uint2(l01, l23);
        *(uint2*)(smc + SM_BH + off) = *(const uint2*)&Wt[row * 64 + sq * 2];
        *(uint2*)(smc + SM_BL + off) = *(const uint2*)&Wt[8192 + row * 64 + sq * 2];
    }
    __syncthreads();
#pragma unroll
    for (int it = 0; it < 4; it++) {
        int row = it * 32 + srow;
        pf[it] = (bm + row < N_NODES)
                 ? *(const float4*)&A2[(long long)(bm + row) * 128 + 32 + sq * 4]
                 : make_float4(0.f, 0.f, 0.f, 0.f);
    }

    const int aRow16 = lane & 15;
    const uint32_t aSel = (uint32_t)(lane >> 4) * 16u;
    const int bRowP = (lane & 7) + ((lane >> 4) << 3);
    const uint32_t bK = (uint32_t)((lane >> 3) & 1) * 16u;

#pragma unroll
    for (int c = 0; c < 4; c++) {
        const uint32_t curB = (uint32_t)(c & 1) * BUFSZ;
        const uint32_t nxtB = curB ^ BUFSZ;

        if (c < 3) {
            const int k0w = (c + 1) * 16;
#pragma unroll
            for (int it = 0; it < 4; it++) {
                int row = it * 32 + srow;
                uint32_t off = nxtB + (uint32_t)(row * RSTR + sq * 8);
                float4 v = pf[it];
                uint32_t h01, l01, h23, l23;
                split2(v.x, v.y, h01, l01);
                split2(v.z, v.w, h23, l23);
                *(uint2*)(smc + SM_AH + off) = make_uint2(h01, h23);
                *(uint2*)(smc + SM_AL + off) = make_uint2(l01, l23);
                *(uint2*)(smc + SM_BH + off) = *(const uint2*)&Wt[row * 64 + k0w + sq * 2];
                *(uint2*)(smc + SM_BL + off) = *(const uint2*)&Wt[8192 + row * 64 + k0w + sq * 2];
            }
        }
        if (c < 2) {
            const int k0n = (c + 2) * 32;
#pragma unroll
            for (int it = 0; it < 4; it++) {
                int row = it * 32 + srow;
                pf[it] = (bm + row < N_NODES)
                         ? *(const float4*)&A2[(long long)(bm + row) * 128 + k0n + sq * 4]
                         : make_float4(0.f, 0.f, 0.f, 0.f);
            }
        }

#pragma unroll
        for (int ks = 0; ks < 2; ks++) {
            uint32_t ah[2][4], al[2][4];
#pragma unroll
            for (int mt = 0; mt < 2; mt++) {
                uint32_t base = sbase + curB + (uint32_t)((mbase + mt * 16 + aRow16) * RSTR)
                              + (uint32_t)ks * 32u + aSel;
                ldsm_x4(ah[mt], base + SM_AH);
                ldsm_x4(al[mt], base + SM_AL);
            }
#pragma unroll
            for (int ntp = 0; ntp < 4; ntp++) {
                uint32_t bb = sbase + curB + (uint32_t)((nbase + ntp * 16 + bRowP) * RSTR)
                            + (uint32_t)ks * 32u + bK;
                uint32_t bh[4], bl[4];
                ldsm_x4(bh, bb + SM_BH);
                ldsm_x4(bl, bb + SM_BL);
                const int nt0 = 2 * ntp;
                const int nt1 = nt0 + 1;
#pragma unroll
                for (int mt = 0; mt < 2; mt++) {
                    mma_bf16(acc[mt][nt0], ah[mt], bh[0], bh[1]);
                    mma_bf16(acc[mt][nt0], ah[mt], bl[0], bl[1]);
                    mma_bf16(acc[mt][nt0], al[mt], bh[0], bh[1]);
                    mma_bf16(acc[mt][nt1], ah[mt], bh[2], bh[3]);
                    mma_bf16(acc[mt][nt1], ah[mt], bl[2], bl[3]);
                    mma_bf16(acc[mt][nt1], al[mt], bh[2], bh[3]);
                }
            }
        }
        __syncthreads();
    }

    // epilogue: partial = acc + bias (no relu)
#pragma unroll
    for (int mt = 0; mt < 2; mt++) {
        int row0 = bm + mbase + mt * 16 + g;
        int row1 = row0 + 8;
#pragma unroll
        for (int nt = 0; nt < 8; nt++) {
            int col = nbase + nt * 8 + 2 * tg;
            float b0 = bias[col];
            float b1 = bias[col + 1];
            if (row0 < N_NODES) {
                float2 o;
                o.x = acc[mt][nt][0] + b0;
                o.y = acc[mt][nt][1] + b1;
                *(float2*)&C[(long long)row0 * 128 + col] = o;
            }
            if (row1 < N_NODES) {
                float2 o;
                o.x = acc[mt][nt][2] + b0;
                o.y = acc[mt][nt][3] + b1;
                *(float2*)&C[(long long)row1 * 128 + col] = o;
            }
        }
    }
}

// h' = relu( agg @ W1 + partial )   (A staged by pure plane copies)
__global__ __launch_bounds__(256, 2)
void k_gemm_a(const uint32_t* __restrict__ A1h, const uint32_t* __restrict__ A1l,
              const uint32_t* __restrict__ Wt,   // W1 tiles: hi at 0, lo at +8192
              float* __restrict__ C) {
    extern __shared__ __align__(16) char smc[];
    const uint32_t sbase = smem_u32(smc);
    const int tid = threadIdx.x;
    const int w = tid >> 5;
    const int lane = tid & 31;
    const int g = lane >> 2;
    const int tg = lane & 3;
    const int bm = blockIdx.x * 128;
    const int mbase = (w & 3) * 32;
    const int nbase = (w >> 2) * 64;

    float acc[2][8][4];
#pragma unroll
    for (int mt = 0; mt < 2; mt++)
#pragma unroll
        for (int nt = 0; nt < 8; nt++)
#pragma unroll
            for (int q = 0; q < 4; q++) acc[mt][nt][q] = 0.f;

    const int srow = tid >> 3;
    const int sq = tid & 7;

    uint2 ph[4], pl[4];
#pragma unroll
    for (int it = 0; it < 4; it++) {
        int row = it * 32 + srow;
        if (bm + row < N_NODES) {
            ph[it] = *(const uint2*)&A1h[(long long)(bm + row) * 64 + sq * 2];
            pl[it] = *(const uint2*)&A1l[(long long)(bm + row) * 64 + sq * 2];
        } else {
            ph[it] = make_uint2(0u, 0u);
            pl[it] = make_uint2(0u, 0u);
        }
    }
#pragma unroll
    for (int it = 0; it < 4; it++) {
        int row = it * 32 + srow;
        uint32_t off = (uint32_t)(row * RSTR + sq * 8);
        *(uint2*)(smc + SM_AH + off) = ph[it];
        *(uint2*)(smc + SM_AL + off) = pl[it];
        *(uint2*)(smc + SM_BH + off) = *(const uint2*)&Wt[row * 64 + sq * 2];
        *(uint2*)(smc + SM_BL + off) = *(const uint2*)&Wt[8192 + row * 64 + sq * 2];
    }
    __syncthreads();
#pragma unroll
    for (int it = 0; it < 4; it++) {
        int row = it * 32 + srow;
        if (bm + row < N_NODES) {
            ph[it] = *(const uint2*)&A1h[(long long)(bm + row) * 64 + 16 + sq * 2];
            pl[it] = *(const uint2*)&A1l[(long long)(bm + row) * 64 + 16 + sq * 2];
        } else {
            ph[it] = make_uint2(0u, 0u);
            pl[it] = make_uint2(0u, 0u);
        }
    }

    const int aRow16 = lane & 15;
    const uint32_t aSel = (uint32_t)(lane >> 4) * 16u;
    const int bRowP = (lane & 7) + ((lane >> 4) << 3);
    const uint32_t bK = (uint32_t)((lane >> 3) & 1) * 16u;

#pragma unroll
    for (int c = 0; c < 4; c++) {
        const uint32_t curB = (uint32_t)(c & 1) * BUFSZ;
        const uint32_t nxtB = curB ^ BUFSZ;

        if (c < 3) {
            const int k0w = (c + 1) * 16;
#pragma unroll
            for (int it = 0; it < 4; it++) {
                int row = it * 32 + srow;
                uint32_t off = nxtB + (uint32_t)(row * RSTR + sq * 8);
                *(uint2*)(smc + SM_AH + off) = ph[it];
                *(uint2*)(smc + SM_AL + off) = pl[it];
                *(uint2*)(smc + SM_BH + off) = *(const uint2*)&Wt[row * 64 + k0w + sq * 2];
                *(uint2*)(smc + SM_BL + off) = *(const uint2*)&Wt[8192 + row * 64 + k0w + sq * 2];
            }
        }
        if (c < 2) {
            const int k0p = (c + 2) * 16;
#pragma unroll
            for (int it = 0; it < 4; it++) {
                int row = it * 32 + srow;
                if (bm + row < N_NODES) {
                    ph[it] = *(const uint2*)&A1h[(long long)(bm + row) * 64 + k0p + sq * 2];
                    pl[it] = *(const uint2*)&A1l[(long long)(bm + row) * 64 + k0p + sq * 2];
                } else {
                    ph[it] = make_uint2(0u, 0u);
                    pl[it] = make_uint2(0u, 0u);
                }
            }
        }

#pragma unroll
        for (int ks = 0; ks < 2; ks++) {
            uint32_t ah[2][4], al[2][4];
#pragma unroll
            for (int mt = 0; mt < 2; mt++) {
                uint32_t base = sbase + curB + (uint32_t)((mbase + mt * 16 + aRow16) * RSTR)
                              + (uint32_t)ks * 32u + aSel;
                ldsm_x4(ah[mt], base + SM_AH);
                ldsm_x4(al[mt], base + SM_AL);
            }
#pragma unroll
            for (int ntp = 0; ntp < 4; ntp++) {
                uint32_t bb = sbase + curB + (uint32_t)((nbase + ntp * 16 + bRowP) * RSTR)
                            + (uint32_t)ks * 32u + bK;
                uint32_t bh[4], bl[4];
                ldsm_x4(bh, bb + SM_BH);
                ldsm_x4(bl, bb + SM_BL);
                const int nt0 = 2 * ntp;
                const int nt1 = nt0 + 1;
#pragma unroll
                for (int mt = 0; mt < 2; mt++) {
                    mma_bf16(acc[mt][nt0], ah[mt], bh[0], bh[1]);
                    mma_bf16(acc[mt][nt0], ah[mt], bl[0], bl[1]);
                    mma_bf16(acc[mt][nt0], al[mt], bh[0], bh[1]);
                    mma_bf16(acc[mt][nt1], ah[mt], bh[2], bh[3]);
                    mma_bf16(acc[mt][nt1], ah[mt], bl[2], bl[3]);
                    mma_bf16(acc[mt][nt1], al[mt], bh[2], bh[3]);
                }
            }
        }
        __syncthreads();
    }

    // epilogue: h' = relu(acc + partial)
#pragma unroll
    for (int mt = 0; mt < 2; mt++) {
        int row0 = bm + mbase + mt * 16 + g;
        int row1 = row0 + 8;
#pragma unroll
        for (int nt = 0; nt < 8; nt++) {
            int col = nbase + nt * 8 + 2 * tg;
            if (row0 < N_NODES) {
                float2 pr = *(const float2*)&C[(long long)row0 * 128 + col];
                float2 o;
                o.x = fmaxf(acc[mt][nt][0] + pr.x, 0.f);
                o.y = fmaxf(acc[mt][nt][1] + pr.y, 0.f);
                *(float2*)&C[(long long)row0 * 128 + col] = o;
            }
            if (row1 < N_NODES) {
                float2 pr = *(const float2*)&C[(long long)row1 * 128 + col];
                float2 o;
                o.x = fmaxf(acc[mt][nt][2] + pr.x, 0.f);
                o.y = fmaxf(acc[mt][nt][3] + pr.y, 0.f);
                *(float2*)&C[(long long)row1 * 128 + col] = o;
            }
        }
    }
}

// ---------------- pooling / SNN / fusion ----------------
__global__ void k_zero_pool() {
    int i = blockIdx.x * blockDim.x + threadIdx.x;
    if (i < N_GRAPHS * D) g_pool[i] = 0.f;
    if (i < N_GRAPHS) g_cnt[i] = 0.f;
}

#define PCHUNK 256
__global__ void k_pool(const float* __restrict__ h, const void* bt) {
    int blk = blockIdx.x;
    int f = threadIdx.x;
    int start = blk * PCHUNK;
    if (start >= N_NODES) return;
    int end = start + PCHUNK;
    if (end > N_NODES) end = N_NODES;
    int is64 = g_flags[1];
    int cur = ld_idx(bt, start, is64);
    float s = 0.f, c = 0.f;
    for (int n = start; n < end; n++) {
        int g = ld_idx(bt, n, is64);
        if (g != cur) {
            atomicAdd(&g_pool[cur * D + f], s);
            if (f == 0) atomicAdd(&g_cnt[cur], c);
            s = 0.f; c = 0.f; cur = g;
        }
        s += h[(long long)n * D + f];
        c += 1.f;
    }
    atomicAdd(&g_pool[cur * D + f], s);
    if (f == 0) atomicAdd(&g_cnt[cur], c);
}

__global__ void k_snn1(const float* __restrict__ x, const float* __restrict__ w1,
                       const float* __restrict__ b1) {
    int g = blockIdx.x;
    int t = threadIdx.x;   // 256
    __shared__ float xs[SNN_IN];
    for (int i = t; i < SNN_IN; i += 256) xs[i] = x[g * SNN_IN + i];
    __syncthreads();
    for (int j = t; j < SNN_HID; j += 256) {
        float a = b1[j];
        for (int k = 0; k < SNN_IN; k++)
            a += xs[k] * w1[k * SNN_HID + j];
        g_snnh[g * SNN_HID + j] = fmaxf(a, 0.f);
    }
}

__global__ void k_final(const float* __restrict__ lin_w, const float* __restrict__ lin_b,
                        const float* __restrict__ w2, const float* __restrict__ b2,
                        const float* __restrict__ fuse_w, const float* __restrict__ fuse_b,
                        float* __restrict__ out) {
    int g = blockIdx.x;
    int t = threadIdx.x;   // 128
    __shared__ float mean[D];
    __shared__ float red[128];
    __shared__ float snl[N_CLASSES], gnl[N_CLASSES];
    float cnt = fmaxf(g_cnt[g], 1.f);
    mean[t] = g_pool[g * D + t] / cnt;
    __syncthreads();
    for (int c = 0; c < N_CLASSES; c++) {
        red[t] = mean[t] * lin_w[t * N_CLASSES + c];
        for (int off = 64; off > 0; off >>= 1) {
            __syncthreads();
            if (t < off) red[t] += red[t + off];
        }
        __syncthreads();
        if (t == 0) gnl[c] = red[0] + lin_b[c];
        __syncthreads();
    }
    for (int c = 0; c < N_CLASSES; c++) {
        float p = 0.f;
        for (int k = t; k < SNN_HID; k += 128)
            p += g_snnh[g * SNN_HID + k] * w2[k * N_CLASSES + c];
        red[t] = p;
        for (int off = 64; off > 0; off >>= 1) {
            __syncthreads();
            if (t < off) red[t] += red[t + off];
        }
        __syncthreads();
        if (t == 0) snl[c] = SNN_BETA * (red[0] + b2[c]);
        __syncthreads();
    }
    if (t < N_CLASSES) {
        float o = fuse_b[t];
        for (int j = 0; j < N_CLASSES; j++) {
            o += snl[j] * fuse_w[j * N_CLASSES + t];
            o += gnl[j] * fuse_w[(N_CLASSES + j) * N_CLASSES + t];
        }
        out[g * N_CLASSES + t] = o;
    }
}

// ---------------- stream/event infrastructure (created pre-checkpoint) --------
struct HxStreams {
    cudaStream_t s2;
    cudaEvent_t eA, eW;
    HxStreams() {
        cudaStreamCreateWithFlags(&s2, cudaStreamNonBlocking);
        cudaEventCreateWithFlags(&eA, cudaEventDisableTiming);
        cudaEventCreateWithFlags(&eW, cudaEventDisableTiming);
        // warm all lazy resources pre-checkpoint
        k_noop<<<1, 1>>>();
        cudaEventRecord(eA, 0);
        cudaStreamWaitEvent(s2, eA, 0);
        k_noop<<<1, 1, 0, s2>>>();
        cudaEventRecord(eW, s2);
        cudaStreamWaitEvent(0, eW, 0);
        cudaDeviceSynchronize();
    }
};
static HxStreams g_hx;

// ---------------- launch ----------------
extern "C" void kernel_launch(void* const* d_in, const int* in_sizes, int n_in,
                              void* d_out, int out_size) {
    const float* snn_x  = (const float*)d_in[0];
    const float* x      = (const float*)d_in[1];
    const void*  ei     = d_in[2];
    const void*  bt     = d_in[3];
    const float* snn_w1 = (const float*)d_in[4];
    const float* snn_b1 = (const float*)d_in[5];
    const float* snn_w2 = (const float*)d_in[6];
    const float* snn_b2 = (const float*)d_in[7];
    const float* wrel   = (const float*)d_in[8];
    const float* wroot  = (const float*)d_in[9];
    const float* brel   = (const float*)d_in[10];
    const float* lin_w  = (const float*)d_in[11];
    const float* lin_b  = (const float*)d_in[12];
    const float* fuse_w = (const float*)d_in[13];
    const float* fuse_b = (const float*)d_in[14];
    float* out = (float*)d_out;

    void* p;
    cudaGetSymbolAddress(&p, g_h0);   float* h0  = (float*)p;
    cudaGetSymbolAddress(&p, g_h1);   float* h1  = (float*)p;
    cudaGetSymbolAddress(&p, g_ah);   uint32_t* ah = (uint32_t*)p;
    cudaGetSymbolAddress(&p, g_al);   uint32_t* al = (uint32_t*)p;
    cudaGetSymbolAddress(&p, g_wsp);  uint32_t* wsp = (uint32_t*)p;

    cudaFuncSetAttribute(k_gemm_h, cudaFuncAttributeMaxDynamicSharedMemorySize, GEMM_SMEM);
    cudaFuncSetAttribute(k_gemm_a, cudaFuncAttributeMaxDynamicSharedMemorySize, GEMM_SMEM);

    // SNN branch runs on s2 while CSR build proceeds on default
    k_snn1<<<N_GRAPHS, 256, 0, g_hx.s2>>>(snn_x, snn_w1, snn_b1);

    k_detect<<<1, 256>>>((const unsigned int*)ei, (const unsigned int*)bt);
    k_wprep<<<(N_LAYERS * 2 * D * (D / 2) + 255) / 256, 256>>>(wrel, wroot);

    // CSR build (by dst)
    k_zero_counts<<<(N_NODES + 255) / 256, 256>>>();
    k_hist<<<(N_EDGES + 255) / 256, 256>>>(ei);
    const int nsb = (N_NODES + 1023) / 1024;   // 98
    k_scan1<<<nsb, 1024>>>();
    k_scan2<<<1, 1>>>(nsb);
    k_scan3<<<(N_NODES + 255) / 256, 256>>>();
    k_scatter<<<(N_EDGES + 255) / 256, 256>>>(ei);
    // s2's GEMM chain must start after CSR+wprep are done (it reads wsp; agg order via events)
    cudaEventRecord(g_hx.eW, 0);
    cudaStreamWaitEvent(g_hx.s2, g_hx.eW, 0);

    // 7 GraphConv layers: per layer,
    //   default: k_agg (needs h_l)      -> record eA
    //   s2:      k_gemm_h (needs h_l only; ordered after previous k_gemm_a in-stream)
    //            wait eA -> k_gemm_a    -> record eW
    //   default: wait eW (h_{l+1} ready for next agg)
    const float* hin = x;
    float* hout = h1;
    const int aggBlocks = (N_NODES * 32 + 255) / 256;
    const int gemmBlocks = (N_NODES + 127) / 128;   // 782
    for (int l = 0; l < N_LAYERS; l++) {
        const uint32_t* wl = wsp + (long long)l * 4 * 8192;

        k_agg<<<aggBlocks, 256>>>(hin, ah, al);
        cudaEventRecord(g_hx.eA, 0);

        k_gemm_h<<<gemmBlocks, 256, GEMM_SMEM, g_hx.s2>>>(hin, wl + 2 * 8192,
                                                          brel + (long long)l * D, hout);
        cudaStreamWaitEvent(g_hx.s2, g_hx.eA, 0);
        k_gemm_a<<<gemmBlocks, 256, GEMM_SMEM, g_hx.s2>>>(ah, al, wl, hout);
        cudaEventRecord(g_hx.eW, g_hx.s2);
        cudaStreamWaitEvent(0, g_hx.eW, 0);

        hin = hout;
        hout = (hout == h1) ? h0 : h1;
    }

    // global mean pool
    k_zero_pool<<<(N_GRAPHS * D + 255) / 256, 256>>>();
    k_pool<<<(N_NODES + PCHUNK - 1) / PCHUNK, 128>>>(hin, bt);

    // fusion (snn done long before on s2; ordered via eW chain)
    k_final<<<N_GRAPHS, 128>>>(lin_w, lin_b, snn_w2, snn_b2, fuse_w, fuse_b, out);
}

// round 16
// speedup vs baseline: 1.1296x; 1.1296x over previous
#include <cuda_runtime.h>
#include <cuda_fp16.h>
#include <cstdint>

#define N_NODES  100000
#define N_EDGES  1600000
#define D        128
#define N_LAYERS 7
#define N_GRAPHS 64
#define N_CLASSES 10
#define SNN_IN   512
#define SNN_HID  1024
#define SNN_BETA 0.85f
#define HSCALE     0.015625f   // 1/64: h stored as h*HSCALE in fp16
#define HSCALE_INV 64.0f

// ---------------- scratch (no allocations allowed) ----------------
__device__ uint32_t g_hf0[N_NODES * 64];   // h_s as half2 (2 vals/word)
__device__ uint32_t g_hf1[N_NODES * 64];
__device__ uint32_t g_ah[N_NODES * 64];    // agg_s hi plane (bf16x2)
__device__ uint32_t g_al[N_NODES * 64];    // agg_s lo plane
__device__ int   g_counts[N_NODES];
__device__ int   g_rowptr[N_NODES + 1];
__device__ int   g_wptr[N_NODES];
__device__ int   g_esrc[N_EDGES];
__device__ int   g_blocksums[256];
__device__ float g_pool[N_GRAPHS * D];
__device__ float g_cnt[N_GRAPHS];
__device__ float g_snnh[N_GRAPHS * SNN_HID];
__device__ int   g_flags[2];   // [0]: edge_index is int64, [1]: batch is int64
// packed bf16x2 split weights (x64 scaled): [l][mat][part][n][kword]
__device__ uint32_t g_wsp[N_LAYERS * 2 * 2 * D * (D / 2)];

// ---------------- portable tensor-core helpers (sm_80+ ISA only) ----------------
__device__ __forceinline__ uint32_t pack_bf16(float lo, float hi) {
    uint32_t r;
    asm("cvt.rn.bf16x2.f32 %0, %1, %2;" : "=r"(r) : "f"(hi), "f"(lo));
    return r;
}
__device__ __forceinline__ void mma_bf16(float* d, const uint32_t* a, uint32_t b0, uint32_t b1) {
    asm volatile(
        "mma.sync.aligned.m16n8k16.row.col.f32.bf16.bf16.f32 "
        "{%0,%1,%2,%3}, {%4,%5,%6,%7}, {%8,%9}, {%0,%1,%2,%3};"
        : "+f"(d[0]), "+f"(d[1]), "+f"(d[2]), "+f"(d[3])
        : "r"(a[0]), "r"(a[1]), "r"(a[2]), "r"(a[3]), "r"(b0), "r"(b1));
}
__device__ __forceinline__ void ldsm_x4(uint32_t* r, uint32_t addr) {
    asm volatile("ldmatrix.sync.aligned.m8n8.x4.shared.b16 {%0,%1,%2,%3}, [%4];"
        : "=r"(r[0]), "=r"(r[1]), "=r"(r[2]), "=r"(r[3]) : "r"(addr));
}
__device__ __forceinline__ uint32_t smem_u32(const void* p) {
    uint32_t a;
    asm("{ .reg .u64 t; cvta.to.shared.u64 t, %1; cvt.u32.u64 %0, t; }" : "=r"(a) : "l"(p));
    return a;
}
// split two floats into packed bf16 hi word + residual lo word
__device__ __forceinline__ void split2(float f0, float f1, uint32_t& hw, uint32_t& lw) {
    hw = pack_bf16(f0, f1);
    float f0h = __uint_as_float(hw << 16);
    float f1h = __uint_as_float(hw & 0xFFFF0000u);
    lw = pack_bf16(f0 - f0h, f1 - f1h);
}
__device__ __forceinline__ float2 h2lo_f2(uint32_t w) {
    __half2 h = *(__half2*)&w;
    return __half22float2(h);
}

// ---------------- index-width helpers ----------------
__device__ __forceinline__ int ld_idx(const void* p, long long i, int is64) {
    if (is64) return (int)((const long long*)p)[i];
    return ((const int*)p)[i];
}

// Parallel dtype detection
__global__ void k_detect(const unsigned int* ei, const unsigned int* bt) {
    __shared__ int e64s, b64s;
    int t = threadIdx.x;   // 256
    if (t == 0) { e64s = 1; b64s = 1; }
    __syncthreads();
    if (ei[2 * t + 1] != 0u) e64s = 0;
    if (bt[99999 - 2 * t] != 0u) b64s = 0;
    __syncthreads();
    if (t == 0) { g_flags[0] = e64s; g_flags[1] = b64s; }
}

// x (fp32) -> scaled fp16 half2 buffer, once
__global__ void k_x2h(const float* __restrict__ x, uint32_t* __restrict__ hf) {
    int i = blockIdx.x * 256 + threadIdx.x;
    if (i >= N_NODES * 64) return;
    float2 v = *(const float2*)&x[(long long)i * 2];
    __half2 h = __floats2half2_rn(v.x * HSCALE, v.y * HSCALE);
    hf[i] = *(uint32_t*)&h;
}

// Transpose + x64-scale + bf16 hi/lo split of all layer weights.
__global__ void k_wprep(const float* __restrict__ wrel, const float* __restrict__ wroot) {
    int idx = blockIdx.x * 256 + threadIdx.x;
    const int WORDS = N_LAYERS * 2 * D * (D / 2);   // 114688
    if (idx >= WORDS) return;
    int l = idx >> 14;
    int rem = idx & 16383;
    int mat = rem >> 13;
    int r2 = rem & 8191;
    int n = r2 >> 6;
    int wk = r2 & 63;
    int k = wk * 2;
    const float* W = (mat ? wroot : wrel) + (long long)l * D * D;
    float f0 = W[k * D + n] * HSCALE_INV;
    float f1 = W[(k + 1) * D + n] * HSCALE_INV;
    uint32_t hw, lw;
    split2(f0, f1, hw, lw);
    int base = ((l * 2 + mat) * 2) * 8192 + n * 64 + wk;
    g_wsp[base] = hw;
    g_wsp[base + 8192] = lw;
}

// ---------------- CSR build ----------------
__global__ void k_zero_counts() {
    int i = blockIdx.x * blockDim.x + threadIdx.x;
    if (i < N_NODES) g_counts[i] = 0;
}
__global__ void k_hist(const void* ei) {
    int e = blockIdx.x * blockDim.x + threadIdx.x;
    if (e >= N_EDGES) return;
    int dst = ld_idx(ei, (long long)N_EDGES + e, g_flags[0]);
    atomicAdd(&g_counts[dst], 1);
}
__global__ void k_scan1() {
    __shared__ int s[1024];
    int blk = blockIdx.x, t = threadIdx.x;
    int idx = blk * 1024 + t;
    int v = (idx < N_NODES) ? g_counts[idx] : 0;
    s[t] = v;
    __syncthreads();
    for (int off = 1; off < 1024; off <<= 1) {
        int add = (t >= off) ? s[t - off] : 0;
        __syncthreads();
        s[t] += add;
        __syncthreads();
    }
    if (idx < N_NODES) g_rowptr[idx] = s[t];
    if (t == 1023) g_blocksums[blk] = s[t];
}
__global__ void k_scan2(int nblocks) {
    if (blockIdx.x == 0 && threadIdx.x == 0) {
        int acc = 0;
        for (int b = 0; b < nblocks; b++) { int v = g_blocksums[b]; g_blocksums[b] = acc; acc += v; }
        g_rowptr[N_NODES] = N_EDGES;
    }
}
__global__ void k_scan3() {
    int i = blockIdx.x * blockDim.x + threadIdx.x;
    if (i < N_NODES) {
        int ex = g_rowptr[i] - g_counts[i] + g_blocksums[i >> 10];
        g_rowptr[i] = ex;
        g_wptr[i] = ex;
    }
}
__global__ void k_scatter(const void* ei) {
    int e = blockIdx.x * blockDim.x + threadIdx.x;
    if (e >= N_EDGES) return;
    int is64 = g_flags[0];
    int src = ld_idx(ei, e, is64);
    int dst = ld_idx(ei, (long long)N_EDGES + e, is64);
    int pos = atomicAdd(&g_wptr[dst], 1);
    g_esrc[pos] = src;
}

// ---------------- aggregation: warp per node over fp16 rows (256B each) ------
__global__ void k_agg(const uint32_t* __restrict__ hf,
                      uint32_t* __restrict__ aggh, uint32_t* __restrict__ aggl) {
    int node = (blockIdx.x * blockDim.x + threadIdx.x) >> 5;
    int lane = threadIdx.x & 31;
    if (node >= N_NODES) return;
    int s = g_rowptr[node];
    int e = g_rowptr[node + 1];
    float4 a0 = make_float4(0.f, 0.f, 0.f, 0.f);
    float4 a1 = make_float4(0.f, 0.f, 0.f, 0.f);
    int i = s;
    for (; i + 4 <= e; i += 4) {
        int s0 = g_esrc[i];
        int s1 = g_esrc[i + 1];
        int s2 = g_esrc[i + 2];
        int s3 = g_esrc[i + 3];
        uint2 w0 = *(const uint2*)&hf[(long long)s0 * 64 + lane * 2];
        uint2 w1 = *(const uint2*)&hf[(long long)s1 * 64 + lane * 2];
        uint2 w2 = *(const uint2*)&hf[(long long)s2 * 64 + lane * 2];
        uint2 w3 = *(const uint2*)&hf[(long long)s3 * 64 + lane * 2];
        float2 q;
        q = h2lo_f2(w0.x); a0.x += q.x; a0.y += q.y;
        q = h2lo_f2(w0.y); a0.z += q.x; a0.w += q.y;
        q = h2lo_f2(w1.x); a1.x += q.x; a1.y += q.y;
        q = h2lo_f2(w1.y); a1.z += q.x; a1.w += q.y;
        q = h2lo_f2(w2.x); a0.x += q.x; a0.y += q.y;
        q = h2lo_f2(w2.y); a0.z += q.x; a0.w += q.y;
        q = h2lo_f2(w3.x); a1.x += q.x; a1.y += q.y;
        q = h2lo_f2(w3.y); a1.z += q.x; a1.w += q.y;
    }
    for (; i < e; i++) {
        int s0 = g_esrc[i];
        uint2 w0 = *(const uint2*)&hf[(long long)s0 * 64 + lane * 2];
        float2 q;
        q = h2lo_f2(w0.x); a0.x += q.x; a0.y += q.y;
        q = h2lo_f2(w0.y); a0.z += q.x; a0.w += q.y;
    }
    a0.x += a1.x; a0.y += a1.y; a0.z += a1.z; a0.w += a1.w;
    uint32_t h01, l01, h23, l23;
    split2(a0.x, a0.y, h01, l01);
    split2(a0.z, a0.w, h23, l23);
    *(uint2*)&aggh[(long long)node * 64 + lane * 2] = make_uint2(h01, h23);
    *(uint2*)&aggl[(long long)node * 64 + lane * 2] = make_uint2(l01, l23);
}

// ---------------- 3xBF16 mma.sync GraphConv GEMM (double-buffered) ----------------
// C_s(fp16) = relu( agg_s @ (64W1) + h_s @ (64W2) + bias ) * (1/64)
#define RSTR 80
#define SM_AH 0
#define SM_AL 10240
#define SM_BH 20480
#define SM_BL 30720
#define BUFSZ 40960
#define GEMM_SMEM (2 * BUFSZ)

__global__ __launch_bounds__(256, 2)
void k_gemm_bf16(const uint32_t* __restrict__ A1h, const uint32_t* __restrict__ A1l,
                 const uint32_t* __restrict__ A2,   // scaled fp16 h, 64 words/row
                 const uint32_t* __restrict__ Wt,   // layer base: 4 tiles of 8192 words
                 const float* __restrict__ bias, uint32_t* __restrict__ C) {
    extern __shared__ __align__(16) char smc[];
    const uint32_t sbase = smem_u32(smc);
    const int tid = threadIdx.x;
    const int w = tid >> 5;
    const int lane = tid & 31;
    const int g = lane >> 2;
    const int tg = lane & 3;
    const int bm = blockIdx.x * 128;
    const int mbase = (w & 3) * 32;
    const int nbase = (w >> 2) * 64;

    float acc[2][8][4];
#pragma unroll
    for (int mt = 0; mt < 2; mt++)
#pragma unroll
        for (int nt = 0; nt < 8; nt++)
#pragma unroll
            for (int q = 0; q < 4; q++) acc[mt][nt][q] = 0.f;

    const int srow = tid >> 3;          // 0..31, +32 per it
    const int sq = tid & 7;             // k-quad (4 k values = 2 words)

    uint2 ph[4], pl[4];                 // plane prefetch (chunks<4), fp16 (chunks>=4: ph only)

    // ---- prologue: load + stage chunk 0 (agg planes) into buf0 ----
#pragma unroll
    for (int it = 0; it < 4; it++) {
        int row = it * 32 + srow;
        if (bm + row < N_NODES) {
            ph[it] = *(const uint2*)&A1h[(long long)(bm + row) * 64 + sq * 2];
            pl[it] = *(const uint2*)&A1l[(long long)(bm + row) * 64 + sq * 2];
        } else {
            ph[it] = make_uint2(0u, 0u);
            pl[it] = make_uint2(0u, 0u);
        }
    }
#pragma unroll
    for (int it = 0; it < 4; it++) {
        int row = it * 32 + srow;
        uint32_t off = (uint32_t)(row * RSTR + sq * 8);
        *(uint2*)(smc + SM_AH + off) = ph[it];
        *(uint2*)(smc + SM_AL + off) = pl[it];
        *(uint2*)(smc + SM_BH + off) = *(const uint2*)&Wt[row * 64 + sq * 2];
        *(uint2*)(smc + SM_BL + off) = *(const uint2*)&Wt[8192 + row * 64 + sq * 2];
    }
    __syncthreads();
    // prefetch chunk 1 (agg planes)
#pragma unroll
    for (int it = 0; it < 4; it++) {
        int row = it * 32 + srow;
        if (bm + row < N_NODES) {
            ph[it] = *(const uint2*)&A1h[(long long)(bm + row) * 64 + 16 + sq * 2];
            pl[it] = *(const uint2*)&A1l[(long long)(bm + row) * 64 + 16 + sq * 2];
        } else {
            ph[it] = make_uint2(0u, 0u);
            pl[it] = make_uint2(0u, 0u);
        }
    }

    // ldmatrix lane addressing
    const int aRow16 = lane & 15;
    const uint32_t aSel = (uint32_t)(lane >> 4) * 16u;
    const int bRowP = (lane & 7) + ((lane >> 4) << 3);     // +8 rows for lanes 16-31
    const uint32_t bK = (uint32_t)((lane >> 3) & 1) * 16u;

#pragma unroll
    for (int c = 0; c < 8; c++) {
        const uint32_t curB = (uint32_t)(c & 1) * BUFSZ;
        const uint32_t nxtB = curB ^ BUFSZ;

        // ---- stage chunk c+1 into buf[nxt] ----
        if (c < 7) {
            const int cn = c + 1;
            const int k0w = (cn & 3) * 16;
            const uint32_t* Whi = Wt + ((cn >> 2) * 2) * 8192;
            const uint32_t* Wlo = Whi + 8192;
#pragma unroll
            for (int it = 0; it < 4; it++) {
                int row = it * 32 + srow;
                uint32_t off = nxtB + (uint32_t)(row * RSTR + sq * 8);
                if (cn < 4) {
                    *(uint2*)(smc + SM_AH + off) = ph[it];
                    *(uint2*)(smc + SM_AL + off) = pl[it];
                } else {
                    // ph[it] holds fp16 words; split exactly to bf16 planes
                    float2 f01 = h2lo_f2(ph[it].x);
                    float2 f23 = h2lo_f2(ph[it].y);
                    uint32_t h01, l01, h23, l23;
                    split2(f01.x, f01.y, h01, l01);
                    split2(f23.x, f23.y, h23, l23);
                    *(uint2*)(smc + SM_AH + off) = make_uint2(h01, h23);
                    *(uint2*)(smc + SM_AL + off) = make_uint2(l01, l23);
                }
                *(uint2*)(smc + SM_BH + off) = *(const uint2*)&Whi[row * 64 + k0w + sq * 2];
                *(uint2*)(smc + SM_BL + off) = *(const uint2*)&Wlo[row * 64 + k0w + sq * 2];
            }
        }
        // ---- prefetch chunk c+2 ----
        if (c < 6) {
            const int cn2 = c + 2;
#pragma unroll
            for (int it = 0; it < 4; it++) {
                int row = it * 32 + srow;
                if (cn2 < 4) {
                    if (bm + row < N_NODES) {
                        ph[it] = *(const uint2*)&A1h[(long long)(bm + row) * 64 + cn2 * 16 + sq * 2];
                        pl[it] = *(const uint2*)&A1l[(long long)(bm + row) * 64 + cn2 * 16 + sq * 2];
                    } else {
                        ph[it] = make_uint2(0u, 0u);
                        pl[it] = make_uint2(0u, 0u);
                    }
                } else {
                    const int k0w2 = (cn2 & 3) * 16;
                    ph[it] = (bm + row < N_NODES)
                             ? *(const uint2*)&A2[(long long)(bm + row) * 64 + k0w2 + sq * 2]
                             : make_uint2(0u, 0u);
                }
            }
        }

        // ---- compute chunk c: 2 k16-steps, B via paired x4 ----
#pragma unroll
        for (int ks = 0; ks < 2; ks++) {
            uint32_t ah[2][4], al[2][4];
#pragma unroll
            for (int mt = 0; mt < 2; mt++) {
                uint32_t base = sbase + curB + (uint32_t)((mbase + mt * 16 + aRow16) * RSTR)
                              + (uint32_t)ks * 32u + aSel;
                ldsm_x4(ah[mt], base + SM_AH);
                ldsm_x4(al[mt], base + SM_AL);
            }
#pragma unroll
            for (int ntp = 0; ntp < 4; ntp++) {
                uint32_t bb = sbase + curB + (uint32_t)((nbase + ntp * 16 + bRowP) * RSTR)
                            + (uint32_t)ks * 32u + bK;
                uint32_t bh[4], bl[4];
                ldsm_x4(bh, bb + SM_BH);
                ldsm_x4(bl, bb + SM_BL);
                const int nt0 = 2 * ntp;
                const int nt1 = nt0 + 1;
#pragma unroll
                for (int mt = 0; mt < 2; mt++) {
                    mma_bf16(acc[mt][nt0], ah[mt], bh[0], bh[1]);
                    mma_bf16(acc[mt][nt0], ah[mt], bl[0], bl[1]);
                    mma_bf16(acc[mt][nt0], al[mt], bh[0], bh[1]);
                    mma_bf16(acc[mt][nt1], ah[mt], bh[2], bh[3]);
                    mma_bf16(acc[mt][nt1], ah[mt], bl[2], bl[3]);
                    mma_bf16(acc[mt][nt1], al[mt], bh[2], bh[3]);
                }
            }
        }
        __syncthreads();
    }

    // ---- epilogue: bias + relu, scaled fp16 stores ----
#pragma unroll
    for (int mt = 0; mt < 2; mt++) {
        int row0 = bm + mbase + mt * 16 + g;
        int row1 = row0 + 8;
#pragma unroll
        for (int nt = 0; nt < 8; nt++) {
            int col = nbase + nt * 8 + 2 * tg;
            float b0 = bias[col];
            float b1 = bias[col + 1];
            if (row0 < N_NODES) {
                float ox = fmaxf(acc[mt][nt][0] + b0, 0.f) * HSCALE;
                float oy = fmaxf(acc[mt][nt][1] + b1, 0.f) * HSCALE;
                __half2 o2 = __floats2half2_rn(ox, oy);
                C[(long long)row0 * 64 + (col >> 1)] = *(uint32_t*)&o2;
            }
            if (row1 < N_NODES) {
                float ox = fmaxf(acc[mt][nt][2] + b0, 0.f) * HSCALE;
                float oy = fmaxf(acc[mt][nt][3] + b1, 0.f) * HSCALE;
                __half2 o2 = __floats2half2_rn(ox, oy);
                C[(long long)row1 * 64 + (col >> 1)] = *(uint32_t*)&o2;
            }
        }
    }
}

// ---------------- pooling / SNN / fusion ----------------
__global__ void k_zero_pool() {
    int i = blockIdx.x * blockDim.x + threadIdx.x;
    if (i < N_GRAPHS * D) g_pool[i] = 0.f;
    if (i < N_GRAPHS) g_cnt[i] = 0.f;
}

#define PCHUNK 256
__global__ void k_pool(const uint32_t* __restrict__ hf, const void* bt) {
    int blk = blockIdx.x;
    int f = threadIdx.x;
    int start = blk * PCHUNK;
    if (start >= N_NODES) return;
    int end = start + PCHUNK;
    if (end > N_NODES) end = N_NODES;
    const __half* hp = (const __half*)hf;
    int is64 = g_flags[1];
    int cur = ld_idx(bt, start, is64);
    float s = 0.f, c = 0.f;
    for (int n = start; n < end; n++) {
        int g = ld_idx(bt, n, is64);
        if (g != cur) {
            atomicAdd(&g_pool[cur * D + f], s * HSCALE_INV);
            if (f == 0) atomicAdd(&g_cnt[cur], c);
            s = 0.f; c = 0.f; cur = g;
        }
        s += __half2float(hp[(long long)n * 128 + f]);
        c += 1.f;
    }
    atomicAdd(&g_pool[cur * D + f], s * HSCALE_INV);
    if (f == 0) atomicAdd(&g_cnt[cur], c);
}

__global__ void k_snn1(const float* __restrict__ x, const float* __restrict__ w1,
                       const float* __restrict__ b1) {
    int g = blockIdx.x;
    int t = threadIdx.x;   // 256
    __shared__ float xs[SNN_IN];
    for (int i = t; i < SNN_IN; i += 256) xs[i] = x[g * SNN_IN + i];
    __syncthreads();
    for (int j = t; j < SNN_HID; j += 256) {
        float a = b1[j];
        for (int k = 0; k < SNN_IN; k++)
            a += xs[k] * w1[k * SNN_HID + j];
        g_snnh[g * SNN_HID + j] = fmaxf(a, 0.f);
    }
}

__global__ void k_final(const float* __restrict__ lin_w, const float* __restrict__ lin_b,
                        const float* __restrict__ w2, const float* __restrict__ b2,
                        const float* __restrict__ fuse_w, const float* __restrict__ fuse_b,
                        float* __restrict__ out) {
    int g = blockIdx.x;
    int t = threadIdx.x;   // 128
    __shared__ float mean[D];
    __shared__ float red[128];
    __shared__ float snl[N_CLASSES], gnl[N_CLASSES];
    float cnt = fmaxf(g_cnt[g], 1.f);
    mean[t] = g_pool[g * D + t] / cnt;
    __syncthreads();
    for (int c = 0; c < N_CLASSES; c++) {
        red[t] = mean[t] * lin_w[t * N_CLASSES + c];
        for (int off = 64; off > 0; off >>= 1) {
            __syncthreads();
            if (t < off) red[t] += red[t + off];
        }
        __syncthreads();
        if (t == 0) gnl[c] = red[0] + lin_b[c];
        __syncthreads();
    }
    for (int c = 0; c < N_CLASSES; c++) {
        float p = 0.f;
        for (int k = t; k < SNN_HID; k += 128)
            p += g_snnh[g * SNN_HID + k] * w2[k * N_CLASSES + c];
        red[t] = p;
        for (int off = 64; off > 0; off >>= 1) {
            __syncthreads();
            if (t < off) red[t] += red[t + off];
        }
        __syncthreads();
        if (t == 0) snl[c] = SNN_BETA * (red[0] + b2[c]);
        __syncthreads();
    }
    if (t < N_CLASSES) {
        float o = fuse_b[t];
        for (int j = 0; j < N_CLASSES; j++) {
            o += snl[j] * fuse_w[j * N_CLASSES + t];
            o += gnl[j] * fuse_w[(N_CLASSES + j) * N_CLASSES + t];
        }
        out[g * N_CLASSES + t] = o;
    }
}

// ---------------- launch ----------------
extern "C" void kernel_launch(void* const* d_in, const int* in_sizes, int n_in,
                              void* d_out, int out_size) {
    const float* snn_x  = (const float*)d_in[0];
    const float* x      = (const float*)d_in[1];
    const void*  ei     = d_in[2];
    const void*  bt     = d_in[3];
    const float* snn_w1 = (const float*)d_in[4];
    const float* snn_b1 = (const float*)d_in[5];
    const float* snn_w2 = (const float*)d_in[6];
    const float* snn_b2 = (const float*)d_in[7];
    const float* wrel   = (const float*)d_in[8];
    const float* wroot  = (const float*)d_in[9];
    const float* brel   = (const float*)d_in[10];
    const float* lin_w  = (const float*)d_in[11];
    const float* lin_b  = (const float*)d_in[12];
    const float* fuse_w = (const float*)d_in[13];
    const float* fuse_b = (const float*)d_in[14];
    float* out = (float*)d_out;

    void* p;
    cudaGetSymbolAddress(&p, g_hf0);  uint32_t* hf0 = (uint32_t*)p;
    cudaGetSymbolAddress(&p, g_hf1);  uint32_t* hf1 = (uint32_t*)p;
    cudaGetSymbolAddress(&p, g_ah);   uint32_t* ah = (uint32_t*)p;
    cudaGetSymbolAddress(&p, g_al);   uint32_t* al = (uint32_t*)p;
    cudaGetSymbolAddress(&p, g_wsp);  uint32_t* wsp = (uint32_t*)p;

    cudaFuncSetAttribute(k_gemm_bf16, cudaFuncAttributeMaxDynamicSharedMemorySize, GEMM_SMEM);

    k_detect<<<1, 256>>>((const unsigned int*)ei, (const unsigned int*)bt);
    k_wprep<<<(N_LAYERS * 2 * D * (D / 2) + 255) / 256, 256>>>(wrel, wroot);
    k_x2h<<<(N_NODES * 64 + 255) / 256, 256>>>(x, hf0);

    // CSR build (by dst)
    k_zero_counts<<<(N_NODES + 255) / 256, 256>>>();
    k_hist<<<(N_EDGES + 255) / 256, 256>>>(ei);
    const int nsb = (N_NODES + 1023) / 1024;   // 98
    k_scan1<<<nsb, 1024>>>();
    k_scan2<<<1, 1>>>(nsb);
    k_scan3<<<(N_NODES + 255) / 256, 256>>>();
    k_scatter<<<(N_EDGES + 255) / 256, 256>>>(ei);

    // 7 GraphConv layers over scaled fp16 h
    const uint32_t* hin = hf0;
    uint32_t* hout = hf1;
    const int aggBlocks = (N_NODES * 32 + 255) / 256;
    const int gemmBlocks = (N_NODES + 127) / 128;   // 782
    for (int l = 0; l < N_LAYERS; l++) {
        k_agg<<<aggBlocks, 256>>>(hin, ah, al);
        k_gemm_bf16<<<gemmBlocks, 256, GEMM_SMEM>>>(ah, al, hin,
                                                    wsp + (long long)l * 4 * 8192,
                                                    brel + (long long)l * D, hout);
        hin = hout;
        hout = (hout == hf1) ? hf0 : hf1;
    }

    // global mean pool
    k_zero_pool<<<(N_GRAPHS * D + 255) / 256, 256>>>();
    k_pool<<<(N_NODES + PCHUNK - 1) / PCHUNK, 128>>>(hin, bt);

    // SNN + fusion
    k_snn1<<<N_GRAPHS, 256>>>(snn_x, snn_w1, snn_b1);
    k_final<<<N_GRAPHS, 128>>>(lin_w, lin_b, snn_w2, snn_b2, fuse_w, fuse_b, out);
}